// round 12
// baseline (speedup 1.0000x reference)
#include <cuda_runtime.h>
#include <cuda_fp16.h>
#include <mma.h>
#include <cstdint>

using namespace nvcuda;

#define NMAX 30000

// ---------------- scratch (no allocation allowed) ----------------
__device__ __half g_featH[NMAX * 128];     // fp16 copy of input feats
__device__ __half g_w0h[3 * 128 * 256];    // fp16 W0
__device__ __half g_w1h[3 * 256 * 256];    // fp16 W1
__device__ __half g_h [NMAX * 768];        // projected feats fp16, [N][t][256]
__device__ __half g_x1h[NMAX * 256];       // layer-0 output (fp16)
__device__ __half g_x2h[NMAX * 256];       // layer-1 output (fp16)
__device__ float  g_el[NMAX * 12];         // [N][t][head]
__device__ float  g_er[NMAX * 12];
__device__ float  g_h2[NMAX * 6];          // layer-2 projected [N][t][2]
__device__ float  g_wal0[24 * 128];        // W0·al / W0·ar composites
__device__ float  g_wal1[24 * 256];        // W1·al / W1·ar composites

// ---------------- fused fp32 -> fp16 conversion (3 segments) ----------------
__global__ __launch_bounds__(256) void f2h_all(
    const float* __restrict__ in0, __half* __restrict__ out0, int n0,
    const float* __restrict__ in1, __half* __restrict__ out1, int n1,
    const float* __restrict__ in2, __half* __restrict__ out2, int n2)
{
    int i = blockIdx.x * blockDim.x + threadIdx.x;   // float4 index
    const float* in; __half* out;
    if (i < n0)            { in = in0; out = out0; }
    else if ((i -= n0) < n1) { in = in1; out = out1; }
    else if ((i -= n1) < n2) { in = in2; out = out2; }
    else return;
    float4 v = reinterpret_cast<const float4*>(in)[i];
    __half2 a = __floats2half2_rn(v.x, v.y);
    __half2 b = __floats2half2_rn(v.z, v.w);
    reinterpret_cast<__half2*>(out)[2 * i + 0] = a;
    reinterpret_cast<__half2*>(out)[2 * i + 1] = b;
}

// ---------------- wal[c][K] = W_t[:,head-block] . a{l,r}  (c = t*4+h, +12 for er)
__global__ __launch_bounds__(128) void prewal(
    const float* __restrict__ W, const float* __restrict__ al,
    const float* __restrict__ ar, float* __restrict__ wal, int K)
{
    const int k = blockIdx.x * 128 + threadIdx.x;
    const int c = blockIdx.y;                 // 0..23
    if (k >= K) return;
    const bool isr = c >= 12;
    const int th = isr ? c - 12 : c;
    const int t = th >> 2, hh = th & 3;
    const float* av = (isr ? ar : al) + t * 256 + hh * 64;
    const float* wp = W + ((size_t)t * K + k) * 256 + hh * 64;
    float s = 0.f;
    #pragma unroll
    for (int d = 0; d < 64; d += 4) {
        float4 w4 = *reinterpret_cast<const float4*>(wp + d);
        float4 a4 = *reinterpret_cast<const float4*>(av + d);
        s += w4.x * a4.x + w4.y * a4.y + w4.z * a4.z + w4.w * a4.w;
    }
    wal[c * K + k] = s;
}

// ---------------- el/er from X directly: warp per node ----------------------
__global__ __launch_bounds__(256) void eler2(
    const __half* __restrict__ X, const float* __restrict__ wal,
    float* __restrict__ el, float* __restrict__ er, int n, int K)
{
    const int w    = (blockIdx.x * blockDim.x + threadIdx.x) >> 5;
    const int lane = threadIdx.x & 31;
    if (w >= n) return;
    const int kpl   = K >> 5;          // 4 (K=128) or 8 (K=256) k's per lane
    const int kbase = lane * kpl;

    float x[8];
    if (kpl == 8) {
        uint4 v = *reinterpret_cast<const uint4*>(X + (size_t)w * K + kbase);
        const __half2* hv = reinterpret_cast<const __half2*>(&v);
        #pragma unroll
        for (int q = 0; q < 4; q++) {
            float2 f = __half22float2(hv[q]); x[2*q] = f.x; x[2*q+1] = f.y;
        }
    } else {
        uint2 v = *reinterpret_cast<const uint2*>(X + (size_t)w * K + kbase);
        const __half2* hv = reinterpret_cast<const __half2*>(&v);
        #pragma unroll
        for (int q = 0; q < 2; q++) {
            float2 f = __half22float2(hv[q]); x[2*q] = f.x; x[2*q+1] = f.y;
        }
        x[4] = x[5] = x[6] = x[7] = 0.f;
    }

    float acc[24];
    #pragma unroll
    for (int c = 0; c < 24; c++) {
        const float* wp = wal + c * K + kbase;
        float4 w0 = __ldg(reinterpret_cast<const float4*>(wp));
        float s = x[0]*w0.x + x[1]*w0.y + x[2]*w0.z + x[3]*w0.w;
        if (kpl == 8) {
            float4 w1 = __ldg(reinterpret_cast<const float4*>(wp + 4));
            s += x[4]*w1.x + x[5]*w1.y + x[6]*w1.z + x[7]*w1.w;
        }
        acc[c] = s;
    }
    #pragma unroll
    for (int o = 16; o > 0; o >>= 1)
        #pragma unroll
        for (int c = 0; c < 24; c++)
            acc[c] += __shfl_xor_sync(0xffffffffu, acc[c], o);

    float v = 0.f;
    #pragma unroll
    for (int c = 0; c < 24; c++) if (lane == c) v = acc[c];
    if (lane < 12)       el[(size_t)w * 12 + lane]      = v;
    else if (lane < 24)  er[(size_t)w * 12 + lane - 12] = v;
}

// ---------------- HMMA GEMM: C_fp16[N,768] = X_fp16[N,K] @ {W_t_fp16[K,256]} ----
#define BM 128
#define BN 128
#define BKH 32
#define APAD 16
#define BPAD 16

__global__ __launch_bounds__(256, 2) void hgemm(
    const __half* __restrict__ X, const __half* __restrict__ W,
    __half* __restrict__ C, int M, int K)
{
    __shared__ __half As[BM][BKH + APAD];
    __shared__ __half Bs[BKH][BN + BPAD];

    const int tid  = threadIdx.x;
    const int wid  = tid >> 5;
    const int lane = tid & 31;
    const int row0 = blockIdx.x * BM;
    const int ct   = blockIdx.y;
    const int t    = ct >> 1;
    const int colbase = (ct & 1) * 128;
    const __half* Wt = W + (size_t)t * K * 256;

    const int wm = wid >> 1;
    const int wn = wid & 1;

    wmma::fragment<wmma::accumulator, 16, 16, 16, float> acc[2][4];
    #pragma unroll
    for (int i = 0; i < 2; i++)
        #pragma unroll
        for (int j = 0; j < 4; j++) wmma::fill_fragment(acc[i][j], 0.0f);

    const int ar = tid >> 1;
    const int as = (tid & 1) * 16;
    const int br = tid >> 3;
    const int bs = (tid & 7) * 16;

    for (int k0 = 0; k0 < K; k0 += BKH) {
        uint4 v0 = make_uint4(0u, 0u, 0u, 0u), v1 = v0;
        if (row0 + ar < M) {
            const __half* xp = X + (size_t)(row0 + ar) * K + k0 + as;
            v0 = *reinterpret_cast<const uint4*>(xp);
            v1 = *reinterpret_cast<const uint4*>(xp + 8);
        }
        *reinterpret_cast<uint4*>(&As[ar][as])     = v0;
        *reinterpret_cast<uint4*>(&As[ar][as + 8]) = v1;

        const __half* wp = Wt + (size_t)(k0 + br) * 256 + colbase + bs;
        *reinterpret_cast<uint4*>(&Bs[br][bs])     = *reinterpret_cast<const uint4*>(wp);
        *reinterpret_cast<uint4*>(&Bs[br][bs + 8]) = *reinterpret_cast<const uint4*>(wp + 8);

        __syncthreads();

        #pragma unroll
        for (int kk = 0; kk < BKH; kk += 16) {
            wmma::fragment<wmma::matrix_a, 16, 16, 16, __half, wmma::row_major> af[2];
            wmma::fragment<wmma::matrix_b, 16, 16, 16, __half, wmma::row_major> bf[4];
            #pragma unroll
            for (int i = 0; i < 2; i++)
                wmma::load_matrix_sync(af[i], &As[wm * 32 + i * 16][kk], BKH + APAD);
            #pragma unroll
            for (int j = 0; j < 4; j++)
                wmma::load_matrix_sync(bf[j], &Bs[kk][wn * 64 + j * 16], BN + BPAD);
            #pragma unroll
            for (int i = 0; i < 2; i++)
                #pragma unroll
                for (int j = 0; j < 4; j++)
                    wmma::mma_sync(acc[i][j], af[i], bf[j], acc[i][j]);
        }
        __syncthreads();
    }

    float* patch = reinterpret_cast<float*>(&As[0][0]) + wid * 256;
    const int pr = lane >> 1;
    const int pc = (lane & 1) * 8;

    #pragma unroll
    for (int i = 0; i < 2; i++) {
        #pragma unroll
        for (int j = 0; j < 4; j++) {
            wmma::store_matrix_sync(patch, acc[i][j], 16, wmma::mem_row_major);
            __syncwarp();
            const int grow = row0 + wm * 32 + i * 16 + pr;
            if (grow < M) {
                __half2 hv[4];
                #pragma unroll
                for (int q = 0; q < 4; q++)
                    hv[q] = __floats2half2_rn(patch[pr * 16 + pc + 2 * q],
                                              patch[pr * 16 + pc + 2 * q + 1]);
                *reinterpret_cast<uint4*>(
                    C + (size_t)grow * 768 + ct * 128 + wn * 64 + j * 16 + pc) =
                    *reinterpret_cast<uint4*>(hv);
            }
            __syncwarp();
        }
    }
}

// ---------------- aggregation: 2 nodes/block, warp-autonomous ----------------
__global__ __launch_bounds__(192) void agg_kernel(
    const __half* __restrict__ h, const float* __restrict__ el,
    const float* __restrict__ er, const int* __restrict__ src,
    const float* __restrict__ bias, __half* __restrict__ xout,
    int n)
{
    const int tid   = threadIdx.x;
    const int local = tid / 96;          // node slot within block (0/1)
    const int wt    = (tid % 96) / 32;   // etype
    const int lane  = tid & 31;
    const int i     = blockIdx.x * 2 + local;
    const int E     = n * 16;

    __shared__ int   s_src [2][3][16];
    __shared__ float s_alpha[2][3][4][16];   // [node][t][head][j]
    __shared__ float s_part[2][3][256];

    if (i < n) {
        int s = 0;
        float a[4] = {0.f, 0.f, 0.f, 0.f};
        if (lane < 16) {
            s = src[(size_t)wt * E + i * 16 + lane];
            s_src[local][wt][lane] = s;
            const float4 el4 = *reinterpret_cast<const float4*>(el + (size_t)s * 12 + wt * 4);
            const float4 er4 = *reinterpret_cast<const float4*>(er + (size_t)i * 12 + wt * 4);
            a[0] = el4.x + er4.x;  a[1] = el4.y + er4.y;
            a[2] = el4.z + er4.z;  a[3] = el4.w + er4.w;
            #pragma unroll
            for (int q = 0; q < 4; q++) a[q] = a[q] > 0.f ? a[q] : 0.2f * a[q];
        }
        #pragma unroll
        for (int q = 0; q < 4; q++) {
            float m = a[q];
            #pragma unroll
            for (int o = 1; o < 16; o <<= 1)
                m = fmaxf(m, __shfl_xor_sync(0xffffffffu, m, o, 16));
            float ex = __expf(a[q] - m);
            float sm = ex;
            #pragma unroll
            for (int o = 1; o < 16; o <<= 1)
                sm += __shfl_xor_sync(0xffffffffu, sm, o, 16);
            a[q] = ex / sm;
        }
        if (lane < 16) {
            #pragma unroll
            for (int q = 0; q < 4; q++) s_alpha[local][wt][q][lane] = a[q];
        }
        __syncwarp();

        const float* ap = s_alpha[local][wt][lane >> 3];
        const __half* hb = h + wt * 256 + lane * 8;
        float acc[8] = {0.f, 0.f, 0.f, 0.f, 0.f, 0.f, 0.f, 0.f};
        #pragma unroll
        for (int j = 0; j < 16; j++) {
            const float aw = ap[j];
            uint4 v = *reinterpret_cast<const uint4*>(
                hb + (size_t)s_src[local][wt][j] * 768);
            const __half2* hv = reinterpret_cast<const __half2*>(&v);
            #pragma unroll
            for (int q = 0; q < 4; q++) {
                float2 f = __half22float2(hv[q]);
                acc[2 * q]     += aw * f.x;
                acc[2 * q + 1] += aw * f.y;
            }
        }
        #pragma unroll
        for (int q = 0; q < 8; q++) s_part[local][wt][lane * 8 + q] = acc[q];
    }
    __syncthreads();

    if (tid < 64) {
        const int nl = tid >> 5, oct = tid & 31;
        const int ii = blockIdx.x * 2 + nl;
        if (ii < n) {
            __half2 hv[4];
            #pragma unroll
            for (int q = 0; q < 4; q++) {
                float r[2];
                #pragma unroll
                for (int u = 0; u < 2; u++) {
                    const int c = oct * 8 + 2 * q + u;
                    float sv = s_part[nl][0][c] + s_part[nl][1][c] + s_part[nl][2][c]
                             + bias[c] + bias[256 + c] + bias[512 + c];
                    sv *= (1.0f / 3.0f);
                    r[u] = sv > 0.f ? sv : (__expf(sv) - 1.0f);
                }
                hv[q] = __floats2half2_rn(r[0], r[1]);
            }
            *reinterpret_cast<uint4*>(xout + (size_t)ii * 256 + oct * 8) =
                *reinterpret_cast<uint4*>(hv);
        }
    }
}

// ---------------- layer-2 projection: warp per row, vectorized -------------
__global__ __launch_bounds__(256) void gemm2_kernel(
    const __half* __restrict__ X, const float* __restrict__ W2,
    float* __restrict__ h2, int n)
{
    const int w    = (blockIdx.x * blockDim.x + threadIdx.x) >> 5;
    const int lane = threadIdx.x & 31;
    if (w >= n) return;

    uint4 v = *reinterpret_cast<const uint4*>(X + (size_t)w * 256 + lane * 8);
    const __half2* hv = reinterpret_cast<const __half2*>(&v);

    float s[6] = {0.f, 0.f, 0.f, 0.f, 0.f, 0.f};
    #pragma unroll
    for (int q = 0; q < 4; q++) {
        float2 f = __half22float2(hv[q]);
        const int d = lane * 8 + 2 * q;
        #pragma unroll
        for (int t = 0; t < 3; t++) {
            s[t * 2 + 0] += f.x * W2[t * 512 + d * 2 + 0] + f.y * W2[t * 512 + (d + 1) * 2 + 0];
            s[t * 2 + 1] += f.x * W2[t * 512 + d * 2 + 1] + f.y * W2[t * 512 + (d + 1) * 2 + 1];
        }
    }
    #pragma unroll
    for (int o = 16; o > 0; o >>= 1)
        #pragma unroll
        for (int q = 0; q < 6; q++)
            s[q] += __shfl_xor_sync(0xffffffffu, s[q], o);
    if (lane < 6) h2[(size_t)w * 6 + lane] = s[lane];
}

// ---------------- final: layer-2 attention + outputs ----------------
__global__ __launch_bounds__(128) void final_kernel(
    const float* __restrict__ h2, const float* __restrict__ al2,
    const float* __restrict__ ar2, const float* __restrict__ b2,
    const int* __restrict__ src, float* __restrict__ out,
    int n, int out_size)
{
    const int i = blockIdx.x * blockDim.x + threadIdx.x;
    if (i >= n) return;
    const int E = n * 16;

    float acc0 = 0.f, acc1 = 0.f;
    for (int t = 0; t < 3; t++) {
        const float2 hi = *reinterpret_cast<const float2*>(h2 + (size_t)i * 6 + t * 2);
        const float eri = hi.x * ar2[t * 2 + 0] + hi.y * ar2[t * 2 + 1];
        const float a0 = al2[t * 2 + 0], a1 = al2[t * 2 + 1];

        float e[16], v0[16], v1[16];
        float mx = -1e30f;
        #pragma unroll
        for (int j = 0; j < 16; j++) {
            const int s = src[(size_t)t * E + i * 16 + j];
            const float2 p = *reinterpret_cast<const float2*>(h2 + (size_t)s * 6 + t * 2);
            v0[j] = p.x; v1[j] = p.y;
            float ev = p.x * a0 + p.y * a1 + eri;
            ev = ev > 0.f ? ev : 0.2f * ev;
            e[j] = ev;
            mx = fmaxf(mx, ev);
        }
        float sum = 0.f;
        #pragma unroll
        for (int j = 0; j < 16; j++) { e[j] = __expf(e[j] - mx); sum += e[j]; }
        const float inv = 1.0f / sum;
        float o0 = 0.f, o1 = 0.f;
        #pragma unroll
        for (int j = 0; j < 16; j++) { o0 += e[j] * v0[j]; o1 += e[j] * v1[j]; }
        acc0 += o0 * inv + b2[t * 2 + 0];
        acc1 += o1 * inv + b2[t * 2 + 1];
    }
    out[(size_t)i * 2 + 0] = acc0 * (1.0f / 3.0f);
    out[(size_t)i * 2 + 1] = acc1 * (1.0f / 3.0f);
    if (out_size >= 4 * n) {
        out[(size_t)n * 2 + i * 2 + 0] = 1.0f;
        out[(size_t)n * 2 + i * 2 + 1] = 1.0f;
    }
}

// ---------------- launch ----------------
extern "C" void kernel_launch(void* const* d_in, const int* in_sizes, int n_in,
                              void* d_out, int out_size)
{
    const float* feat = (const float*)d_in[0];
    const float* W0   = (const float*)d_in[1];
    const float* al0  = (const float*)d_in[2];
    const float* ar0  = (const float*)d_in[3];
    const float* b0   = (const float*)d_in[4];
    const float* W1   = (const float*)d_in[5];
    const float* al1  = (const float*)d_in[6];
    const float* ar1  = (const float*)d_in[7];
    const float* b1   = (const float*)d_in[8];
    const float* W2   = (const float*)d_in[9];
    const float* al2  = (const float*)d_in[10];
    const float* ar2  = (const float*)d_in[11];
    const float* b2   = (const float*)d_in[12];
    const int*   src  = (const int*)d_in[13];
    float* out = (float*)d_out;

    const int n = in_sizes[0] / 128;   // 30000

    __half *featH, *w0h, *w1h, *h, *x1h, *x2h;
    float *el, *er, *h2, *wal0, *wal1;
    cudaGetSymbolAddress((void**)&featH, g_featH);
    cudaGetSymbolAddress((void**)&w0h,   g_w0h);
    cudaGetSymbolAddress((void**)&w1h,   g_w1h);
    cudaGetSymbolAddress((void**)&h,     g_h);
    cudaGetSymbolAddress((void**)&x1h,   g_x1h);
    cudaGetSymbolAddress((void**)&x2h,   g_x2h);
    cudaGetSymbolAddress((void**)&el,    g_el);
    cudaGetSymbolAddress((void**)&er,    g_er);
    cudaGetSymbolAddress((void**)&h2,    g_h2);
    cudaGetSymbolAddress((void**)&wal0,  g_wal0);
    cudaGetSymbolAddress((void**)&wal1,  g_wal1);

    const dim3 ggrid((n + BM - 1) / BM, 6);

    // fused fp16 conversions + el/er weight composites
    const int nf4 = n * 128 / 4;
    const int nw0 = 3 * 128 * 256 / 4;
    const int nw1 = 3 * 256 * 256 / 4;
    f2h_all<<<(nf4 + nw0 + nw1 + 255) / 256, 256>>>(
        feat, featH, nf4, W0, w0h, nw0, W1, w1h, nw1);
    prewal<<<dim3(1, 24), 128>>>(W0, al0, ar0, wal0, 128);
    prewal<<<dim3(2, 24), 128>>>(W1, al1, ar1, wal1, 256);

    // layer 0
    hgemm<<<ggrid, 256>>>(featH, w0h, h, n, 128);
    eler2<<<(n * 32 + 255) / 256, 256>>>(featH, wal0, el, er, n, 128);
    agg_kernel<<<(n + 1) / 2, 192>>>(h, el, er, src, b0, x1h, n);

    // layer 1
    hgemm<<<ggrid, 256>>>(x1h, w1h, h, n, 256);
    eler2<<<(n * 32 + 255) / 256, 256>>>(x1h, wal1, el, er, n, 256);
    agg_kernel<<<(n + 1) / 2, 192>>>(h, el, er, src, b1, x2h, n);

    // layer 2
    gemm2_kernel<<<(n * 32 + 255) / 256, 256>>>(x2h, W2, h2, n);
    final_kernel<<<(n + 127) / 128, 128>>>(h2, al2, ar2, b2, src, out, n, out_size);
}

// round 16
// speedup vs baseline: 1.2117x; 1.2117x over previous
#include <cuda_runtime.h>
#include <cuda_fp16.h>
#include <mma.h>
#include <cstdint>

using namespace nvcuda;

#define NMAX 30000

// ---------------- scratch (no allocation allowed) ----------------
__device__ __half g_featH[NMAX * 128];     // fp16 copy of input feats
__device__ __half g_w0h[3 * 128 * 256];    // fp16 W0
__device__ __half g_w1h[3 * 256 * 256];    // fp16 W1
__device__ __half g_h [NMAX * 768];        // projected feats fp16, [N][t][256]
__device__ __half g_x1h[NMAX * 256];       // layer-0 output (fp16)
__device__ __half g_x2h[NMAX * 256];       // layer-1 output (fp16)
__device__ float  g_elr[NMAX * 32];        // [N][32]: per etype t: [t*8..t*8+4)=el heads, [t*8+4..t*8+8)=er heads
__device__ float  g_h2[NMAX * 6];          // layer-2 projected [N][t][2]
__device__ __half g_walh0[128 * 32];       // W0-composites, [K][32] fp16
__device__ __half g_walh1[256 * 32];       // W1-composites, [K][32] fp16

// ---------------- fused fp32 -> fp16 conversion (3 segments) ----------------
__global__ __launch_bounds__(256) void f2h_all(
    const float* __restrict__ in0, __half* __restrict__ out0, int n0,
    const float* __restrict__ in1, __half* __restrict__ out1, int n1,
    const float* __restrict__ in2, __half* __restrict__ out2, int n2)
{
    int i = blockIdx.x * blockDim.x + threadIdx.x;   // float4 index
    const float* in; __half* out;
    if (i < n0)            { in = in0; out = out0; }
    else if ((i -= n0) < n1) { in = in1; out = out1; }
    else if ((i -= n1) < n2) { in = in2; out = out2; }
    else return;
    float4 v = reinterpret_cast<const float4*>(in)[i];
    __half2 a = __floats2half2_rn(v.x, v.y);
    __half2 b = __floats2half2_rn(v.z, v.w);
    reinterpret_cast<__half2*>(out)[2 * i + 0] = a;
    reinterpret_cast<__half2*>(out)[2 * i + 1] = b;
}

// ---------------- WB[k][c] = sum_d W_t[k, head*64+d] * a{l,r}[t,head,d] ------
// c layout: t = c>>3; (c>>2)&1 selects al/ar; head = c&3. c in [24,32) -> 0.
__global__ __launch_bounds__(128) void prewal_h(
    const float* __restrict__ W, const float* __restrict__ al,
    const float* __restrict__ ar, __half* __restrict__ WB, int K)
{
    const int idx = blockIdx.x * 128 + threadIdx.x;   // k*32 + c
    if (idx >= K * 32) return;
    const int k = idx >> 5, c = idx & 31;
    float s = 0.f;
    if (c < 24) {
        const int t = c >> 3, isr = (c >> 2) & 1, hh = c & 3;
        const float* av = (isr ? ar : al) + t * 256 + hh * 64;
        const float* wp = W + ((size_t)t * K + k) * 256 + hh * 64;
        #pragma unroll
        for (int d = 0; d < 64; d += 4) {
            float4 w4 = *reinterpret_cast<const float4*>(wp + d);
            float4 a4 = *reinterpret_cast<const float4*>(av + d);
            s += w4.x * a4.x + w4.y * a4.y + w4.z * a4.z + w4.w * a4.w;
        }
    }
    WB[idx] = __float2half_rn(s);
}

// ---------------- skinny HMMA: elr[N,32] = X[N,K] @ WB[K,32] ----------------
__global__ __launch_bounds__(256) void elgemm(
    const __half* __restrict__ X, const __half* __restrict__ WB,
    float* __restrict__ elr, int M, int K)
{
    __shared__ __half Xs[128][40];   // 80B rows: odd multiple of 16B -> conflict-free ldsm
    __shared__ __half Ws[32][40];

    const int tid  = threadIdx.x;
    const int wid  = tid >> 5;
    const int lane = tid & 31;
    const int row0 = blockIdx.x * 128;

    wmma::fragment<wmma::accumulator, 16, 16, 16, float> acc[2];
    wmma::fill_fragment(acc[0], 0.0f);
    wmma::fill_fragment(acc[1], 0.0f);

    const int ar = tid >> 1;
    const int as = (tid & 1) * 16;

    for (int k0 = 0; k0 < K; k0 += 32) {
        uint4 v0 = make_uint4(0u, 0u, 0u, 0u), v1 = v0;
        if (row0 + ar < M) {
            const __half* xp = X + (size_t)(row0 + ar) * K + k0 + as;
            v0 = *reinterpret_cast<const uint4*>(xp);
            v1 = *reinterpret_cast<const uint4*>(xp + 8);
        }
        *reinterpret_cast<uint4*>(&Xs[ar][as])     = v0;
        *reinterpret_cast<uint4*>(&Xs[ar][as + 8]) = v1;
        if (tid < 128) {
            const int r = tid >> 2, cs = (tid & 3) * 8;
            *reinterpret_cast<uint4*>(&Ws[r][cs]) =
                *reinterpret_cast<const uint4*>(WB + (size_t)(k0 + r) * 32 + cs);
        }
        __syncthreads();

        #pragma unroll
        for (int kk = 0; kk < 32; kk += 16) {
            wmma::fragment<wmma::matrix_a, 16, 16, 16, __half, wmma::row_major> af;
            wmma::fragment<wmma::matrix_b, 16, 16, 16, __half, wmma::row_major> bf0, bf1;
            wmma::load_matrix_sync(af, &Xs[wid * 16][kk], 40);
            wmma::load_matrix_sync(bf0, &Ws[kk][0], 40);
            wmma::load_matrix_sync(bf1, &Ws[kk][16], 40);
            wmma::mma_sync(acc[0], af, bf0, acc[0]);
            wmma::mma_sync(acc[1], af, bf1, acc[1]);
        }
        __syncthreads();
    }

    float* patch = reinterpret_cast<float*>(&Xs[0][0]) + wid * 256;
    const int pr = lane >> 1;
    const int pc = (lane & 1) * 8;
    #pragma unroll
    for (int j = 0; j < 2; j++) {
        wmma::store_matrix_sync(patch, acc[j], 16, wmma::mem_row_major);
        __syncwarp();
        const int grow = row0 + wid * 16 + pr;
        if (grow < M) {
            *reinterpret_cast<float4*>(elr + (size_t)grow * 32 + j * 16 + pc) =
                *reinterpret_cast<float4*>(&patch[pr * 16 + pc]);
            *reinterpret_cast<float4*>(elr + (size_t)grow * 32 + j * 16 + pc + 4) =
                *reinterpret_cast<float4*>(&patch[pr * 16 + pc + 4]);
        }
        __syncwarp();
    }
}

// ---------------- HMMA GEMM: C_fp16[N,768] = X_fp16[N,K] @ {W_t_fp16[K,256]} ----
#define BM 128
#define BN 128
#define BKH 32
#define APAD 8    // row stride 40 halfs = 80B = 5*16B (odd) -> conflict-free ldsm
#define BPAD 8    // row stride 136 halfs = 272B = 17*16B (odd)

__global__ __launch_bounds__(256, 2) void hgemm(
    const __half* __restrict__ X, const __half* __restrict__ W,
    __half* __restrict__ C, int M, int K)
{
    __shared__ __half As[BM][BKH + APAD];
    __shared__ __half Bs[BKH][BN + BPAD];

    const int tid  = threadIdx.x;
    const int wid  = tid >> 5;
    const int lane = tid & 31;
    const int row0 = blockIdx.x * BM;
    const int ct   = blockIdx.y;
    const int t    = ct >> 1;
    const int colbase = (ct & 1) * 128;
    const __half* Wt = W + (size_t)t * K * 256;

    const int wm = wid >> 1;
    const int wn = wid & 1;

    wmma::fragment<wmma::accumulator, 16, 16, 16, float> acc[2][4];
    #pragma unroll
    for (int i = 0; i < 2; i++)
        #pragma unroll
        for (int j = 0; j < 4; j++) wmma::fill_fragment(acc[i][j], 0.0f);

    const int ar = tid >> 1;
    const int as = (tid & 1) * 16;
    const int br = tid >> 3;
    const int bs = (tid & 7) * 16;

    for (int k0 = 0; k0 < K; k0 += BKH) {
        uint4 v0 = make_uint4(0u, 0u, 0u, 0u), v1 = v0;
        if (row0 + ar < M) {
            const __half* xp = X + (size_t)(row0 + ar) * K + k0 + as;
            v0 = *reinterpret_cast<const uint4*>(xp);
            v1 = *reinterpret_cast<const uint4*>(xp + 8);
        }
        *reinterpret_cast<uint4*>(&As[ar][as])     = v0;
        *reinterpret_cast<uint4*>(&As[ar][as + 8]) = v1;

        const __half* wp = Wt + (size_t)(k0 + br) * 256 + colbase + bs;
        *reinterpret_cast<uint4*>(&Bs[br][bs])     = *reinterpret_cast<const uint4*>(wp);
        *reinterpret_cast<uint4*>(&Bs[br][bs + 8]) = *reinterpret_cast<const uint4*>(wp + 8);

        __syncthreads();

        #pragma unroll
        for (int kk = 0; kk < BKH; kk += 16) {
            wmma::fragment<wmma::matrix_a, 16, 16, 16, __half, wmma::row_major> af[2];
            wmma::fragment<wmma::matrix_b, 16, 16, 16, __half, wmma::row_major> bf[4];
            #pragma unroll
            for (int i = 0; i < 2; i++)
                wmma::load_matrix_sync(af[i], &As[wm * 32 + i * 16][kk], BKH + APAD);
            #pragma unroll
            for (int j = 0; j < 4; j++)
                wmma::load_matrix_sync(bf[j], &Bs[kk][wn * 64 + j * 16], BN + BPAD);
            #pragma unroll
            for (int i = 0; i < 2; i++)
                #pragma unroll
                for (int j = 0; j < 4; j++)
                    wmma::mma_sync(acc[i][j], af[i], bf[j], acc[i][j]);
        }
        __syncthreads();
    }

    float* patch = reinterpret_cast<float*>(&As[0][0]) + wid * 256;
    const int pr = lane >> 1;
    const int pc = (lane & 1) * 8;

    #pragma unroll
    for (int i = 0; i < 2; i++) {
        #pragma unroll
        for (int j = 0; j < 4; j++) {
            wmma::store_matrix_sync(patch, acc[i][j], 16, wmma::mem_row_major);
            __syncwarp();
            const int grow = row0 + wm * 32 + i * 16 + pr;
            if (grow < M) {
                __half2 hv[4];
                #pragma unroll
                for (int q = 0; q < 4; q++)
                    hv[q] = __floats2half2_rn(patch[pr * 16 + pc + 2 * q],
                                              patch[pr * 16 + pc + 2 * q + 1]);
                *reinterpret_cast<uint4*>(
                    C + (size_t)grow * 768 + ct * 128 + wn * 64 + j * 16 + pc) =
                    *reinterpret_cast<uint4*>(hv);
            }
            __syncwarp();
        }
    }
}

// ---------------- aggregation: 2 nodes/block, warp-autonomous ----------------
__global__ __launch_bounds__(192) void agg_kernel(
    const __half* __restrict__ h, const float* __restrict__ elr,
    const int* __restrict__ src, const float* __restrict__ bias,
    __half* __restrict__ xout, int n)
{
    const int tid   = threadIdx.x;
    const int local = tid / 96;          // node slot within block (0/1)
    const int wt    = (tid % 96) / 32;   // etype
    const int lane  = tid & 31;
    const int i     = blockIdx.x * 2 + local;
    const int E     = n * 16;

    __shared__ int   s_src [2][3][16];
    __shared__ float s_alpha[2][3][4][16];   // [node][t][head][j]
    __shared__ float s_part[2][3][256];

    if (i < n) {
        int s = 0;
        float a[4] = {0.f, 0.f, 0.f, 0.f};
        if (lane < 16) {
            s = src[(size_t)wt * E + i * 16 + lane];
            s_src[local][wt][lane] = s;
            const float4 el4 = *reinterpret_cast<const float4*>(elr + (size_t)s * 32 + wt * 8);
            const float4 er4 = *reinterpret_cast<const float4*>(elr + (size_t)i * 32 + wt * 8 + 4);
            a[0] = el4.x + er4.x;  a[1] = el4.y + er4.y;
            a[2] = el4.z + er4.z;  a[3] = el4.w + er4.w;
            #pragma unroll
            for (int q = 0; q < 4; q++) a[q] = a[q] > 0.f ? a[q] : 0.2f * a[q];
        }
        #pragma unroll
        for (int q = 0; q < 4; q++) {
            float m = a[q];
            #pragma unroll
            for (int o = 1; o < 16; o <<= 1)
                m = fmaxf(m, __shfl_xor_sync(0xffffffffu, m, o, 16));
            float ex = __expf(a[q] - m);
            float sm = ex;
            #pragma unroll
            for (int o = 1; o < 16; o <<= 1)
                sm += __shfl_xor_sync(0xffffffffu, sm, o, 16);
            a[q] = ex / sm;
        }
        if (lane < 16) {
            #pragma unroll
            for (int q = 0; q < 4; q++) s_alpha[local][wt][q][lane] = a[q];
        }
        __syncwarp();

        const float* ap = s_alpha[local][wt][lane >> 3];
        const __half* hb = h + wt * 256 + lane * 8;
        float acc[8] = {0.f, 0.f, 0.f, 0.f, 0.f, 0.f, 0.f, 0.f};
        #pragma unroll
        for (int j = 0; j < 16; j++) {
            const float aw = ap[j];
            uint4 v = *reinterpret_cast<const uint4*>(
                hb + (size_t)s_src[local][wt][j] * 768);
            const __half2* hv = reinterpret_cast<const __half2*>(&v);
            #pragma unroll
            for (int q = 0; q < 4; q++) {
                float2 f = __half22float2(hv[q]);
                acc[2 * q]     += aw * f.x;
                acc[2 * q + 1] += aw * f.y;
            }
        }
        #pragma unroll
        for (int q = 0; q < 8; q++) s_part[local][wt][lane * 8 + q] = acc[q];
    }
    __syncthreads();

    if (tid < 64) {
        const int nl = tid >> 5, oct = tid & 31;
        const int ii = blockIdx.x * 2 + nl;
        if (ii < n) {
            __half2 hv[4];
            #pragma unroll
            for (int q = 0; q < 4; q++) {
                float r[2];
                #pragma unroll
                for (int u = 0; u < 2; u++) {
                    const int c = oct * 8 + 2 * q + u;
                    float sv = s_part[nl][0][c] + s_part[nl][1][c] + s_part[nl][2][c]
                             + bias[c] + bias[256 + c] + bias[512 + c];
                    sv *= (1.0f / 3.0f);
                    r[u] = sv > 0.f ? sv : (__expf(sv) - 1.0f);
                }
                hv[q] = __floats2half2_rn(r[0], r[1]);
            }
            *reinterpret_cast<uint4*>(xout + (size_t)ii * 256 + oct * 8) =
                *reinterpret_cast<uint4*>(hv);
        }
    }
}

// ---------------- layer-2 projection: warp per row, vectorized -------------
__global__ __launch_bounds__(256) void gemm2_kernel(
    const __half* __restrict__ X, const float* __restrict__ W2,
    float* __restrict__ h2, int n)
{
    const int w    = (blockIdx.x * blockDim.x + threadIdx.x) >> 5;
    const int lane = threadIdx.x & 31;
    if (w >= n) return;

    uint4 v = *reinterpret_cast<const uint4*>(X + (size_t)w * 256 + lane * 8);
    const __half2* hv = reinterpret_cast<const __half2*>(&v);

    float s[6] = {0.f, 0.f, 0.f, 0.f, 0.f, 0.f};
    #pragma unroll
    for (int q = 0; q < 4; q++) {
        float2 f = __half22float2(hv[q]);
        const int d = lane * 8 + 2 * q;
        #pragma unroll
        for (int t = 0; t < 3; t++) {
            s[t * 2 + 0] += f.x * W2[t * 512 + d * 2 + 0] + f.y * W2[t * 512 + (d + 1) * 2 + 0];
            s[t * 2 + 1] += f.x * W2[t * 512 + d * 2 + 1] + f.y * W2[t * 512 + (d + 1) * 2 + 1];
        }
    }
    #pragma unroll
    for (int o = 16; o > 0; o >>= 1)
        #pragma unroll
        for (int q = 0; q < 6; q++)
            s[q] += __shfl_xor_sync(0xffffffffu, s[q], o);
    if (lane < 6) h2[(size_t)w * 6 + lane] = s[lane];
}

// ---------------- final: layer-2 attention + outputs ----------------
__global__ __launch_bounds__(128) void final_kernel(
    const float* __restrict__ h2, const float* __restrict__ al2,
    const float* __restrict__ ar2, const float* __restrict__ b2,
    const int* __restrict__ src, float* __restrict__ out,
    int n, int out_size)
{
    const int i = blockIdx.x * blockDim.x + threadIdx.x;
    if (i >= n) return;
    const int E = n * 16;

    float acc0 = 0.f, acc1 = 0.f;
    for (int t = 0; t < 3; t++) {
        const float2 hi = *reinterpret_cast<const float2*>(h2 + (size_t)i * 6 + t * 2);
        const float eri = hi.x * ar2[t * 2 + 0] + hi.y * ar2[t * 2 + 1];
        const float a0 = al2[t * 2 + 0], a1 = al2[t * 2 + 1];

        float e[16], v0[16], v1[16];
        float mx = -1e30f;
        #pragma unroll
        for (int j = 0; j < 16; j++) {
            const int s = src[(size_t)t * E + i * 16 + j];
            const float2 p = *reinterpret_cast<const float2*>(h2 + (size_t)s * 6 + t * 2);
            v0[j] = p.x; v1[j] = p.y;
            float ev = p.x * a0 + p.y * a1 + eri;
            ev = ev > 0.f ? ev : 0.2f * ev;
            e[j] = ev;
            mx = fmaxf(mx, ev);
        }
        float sum = 0.f;
        #pragma unroll
        for (int j = 0; j < 16; j++) { e[j] = __expf(e[j] - mx); sum += e[j]; }
        const float inv = 1.0f / sum;
        float o0 = 0.f, o1 = 0.f;
        #pragma unroll
        for (int j = 0; j < 16; j++) { o0 += e[j] * v0[j]; o1 += e[j] * v1[j]; }
        acc0 += o0 * inv + b2[t * 2 + 0];
        acc1 += o1 * inv + b2[t * 2 + 1];
    }
    out[(size_t)i * 2 + 0] = acc0 * (1.0f / 3.0f);
    out[(size_t)i * 2 + 1] = acc1 * (1.0f / 3.0f);
    if (out_size >= 4 * n) {
        out[(size_t)n * 2 + i * 2 + 0] = 1.0f;
        out[(size_t)n * 2 + i * 2 + 1] = 1.0f;
    }
}

// ---------------- launch ----------------
extern "C" void kernel_launch(void* const* d_in, const int* in_sizes, int n_in,
                              void* d_out, int out_size)
{
    const float* feat = (const float*)d_in[0];
    const float* W0   = (const float*)d_in[1];
    const float* al0  = (const float*)d_in[2];
    const float* ar0  = (const float*)d_in[3];
    const float* b0   = (const float*)d_in[4];
    const float* W1   = (const float*)d_in[5];
    const float* al1  = (const float*)d_in[6];
    const float* ar1  = (const float*)d_in[7];
    const float* b1   = (const float*)d_in[8];
    const float* W2   = (const float*)d_in[9];
    const float* al2  = (const float*)d_in[10];
    const float* ar2  = (const float*)d_in[11];
    const float* b2   = (const float*)d_in[12];
    const int*   src  = (const int*)d_in[13];
    float* out = (float*)d_out;

    const int n = in_sizes[0] / 128;   // 30000

    __half *featH, *w0h, *w1h, *h, *x1h, *x2h, *walh0, *walh1;
    float *elr, *h2;
    cudaGetSymbolAddress((void**)&featH, g_featH);
    cudaGetSymbolAddress((void**)&w0h,   g_w0h);
    cudaGetSymbolAddress((void**)&w1h,   g_w1h);
    cudaGetSymbolAddress((void**)&h,     g_h);
    cudaGetSymbolAddress((void**)&x1h,   g_x1h);
    cudaGetSymbolAddress((void**)&x2h,   g_x2h);
    cudaGetSymbolAddress((void**)&elr,   g_elr);
    cudaGetSymbolAddress((void**)&h2,    g_h2);
    cudaGetSymbolAddress((void**)&walh0, g_walh0);
    cudaGetSymbolAddress((void**)&walh1, g_walh1);

    const dim3 ggrid((n + BM - 1) / BM, 6);
    const int egrid = (n + 127) / 128;

    // fused fp16 conversions + el/er composite weights
    const int nf4 = n * 128 / 4;
    const int nw0 = 3 * 128 * 256 / 4;
    const int nw1 = 3 * 256 * 256 / 4;
    f2h_all<<<(nf4 + nw0 + nw1 + 255) / 256, 256>>>(
        feat, featH, nf4, W0, w0h, nw0, W1, w1h, nw1);
    prewal_h<<<(128 * 32 + 127) / 128, 128>>>(W0, al0, ar0, walh0, 128);
    prewal_h<<<(256 * 32 + 127) / 128, 128>>>(W1, al1, ar1, walh1, 256);

    // layer 0
    hgemm<<<ggrid, 256>>>(featH, w0h, h, n, 128);
    elgemm<<<egrid, 256>>>(featH, walh0, elr, n, 128);
    agg_kernel<<<(n + 1) / 2, 192>>>(h, elr, src, b0, x1h, n);

    // layer 1
    hgemm<<<ggrid, 256>>>(x1h, w1h, h, n, 256);
    elgemm<<<egrid, 256>>>(x1h, walh1, elr, n, 256);
    agg_kernel<<<(n + 1) / 2, 192>>>(h, elr, src, b1, x2h, n);

    // layer 2
    gemm2_kernel<<<(n * 32 + 255) / 256, 256>>>(x2h, W2, h2, n);
    final_kernel<<<(n + 127) / 128, 128>>>(h2, al2, ar2, b2, src, out, n, out_size);
}

// round 17
// speedup vs baseline: 1.2793x; 1.0558x over previous
#include <cuda_runtime.h>
#include <cuda_fp16.h>
#include <mma.h>
#include <cstdint>

using namespace nvcuda;

#define NMAX 30000

// ---------------- scratch (no allocation allowed) ----------------
__device__ __half g_featH[NMAX * 128];     // fp16 copy of input feats
__device__ __half g_w0h[3 * 128 * 256];    // fp16 W0
__device__ __half g_w1h[3 * 256 * 256];    // fp16 W1
__device__ __half g_h [NMAX * 768];        // projected feats fp16, [N][t][256]
__device__ __half g_x1h[NMAX * 256];       // layer-0 output (fp16)
__device__ __half g_x2h[NMAX * 256];       // layer-1 output (fp16)
__device__ float  g_elr[NMAX * 32];        // [N][32]: etype t: [t*8,t*8+4)=el, [t*8+4,t*8+8)=er
__device__ float  g_h2[NMAX * 6];          // layer-2 projected [N][t][2]
__device__ __half g_walh0[128 * 32];       // W0-composites, [K][32] fp16
__device__ __half g_walh1[256 * 32];       // W1-composites, [K][32] fp16

// ---------------- cp.async helpers (sm_103a LDGSTS) ----------------
__device__ __forceinline__ uint32_t smaddr(const void* p) {
    return (uint32_t)__cvta_generic_to_shared(p);
}
__device__ __forceinline__ void cp16(uint32_t d, const void* s, int srcsz) {
    asm volatile("cp.async.cg.shared.global [%0], [%1], 16, %2;"
                 :: "r"(d), "l"(s), "r"(srcsz));
}
#define CPC()  asm volatile("cp.async.commit_group;" ::: "memory")
#define CPW(n) asm volatile("cp.async.wait_group %0;" :: "n"(n) : "memory")

// ---------------- fused preprocessing: f2h (3 segs) + prewal (2 layers) -----
// Block ranges: [0,B0) f2h; [B0,B0+16) prewal0; [B0+16,B0+48) prewal1.
__global__ __launch_bounds__(256) void preproc(
    const float* __restrict__ in0, __half* __restrict__ out0, int n0,
    const float* __restrict__ in1, __half* __restrict__ out1, int n1,
    const float* __restrict__ in2, __half* __restrict__ out2, int n2,
    int B0,
    const float* __restrict__ W0, const float* __restrict__ al0,
    const float* __restrict__ ar0, __half* __restrict__ WB0,
    const float* __restrict__ W1, const float* __restrict__ al1,
    const float* __restrict__ ar1, __half* __restrict__ WB1)
{
    const int b = blockIdx.x;
    if (b < B0) {
        int i = b * 256 + threadIdx.x;
        const float* in; __half* out;
        if (i < n0)              { in = in0; out = out0; }
        else if ((i -= n0) < n1) { in = in1; out = out1; }
        else if ((i -= n1) < n2) { in = in2; out = out2; }
        else return;
        float4 v = reinterpret_cast<const float4*>(in)[i];
        reinterpret_cast<__half2*>(out)[2 * i + 0] = __floats2half2_rn(v.x, v.y);
        reinterpret_cast<__half2*>(out)[2 * i + 1] = __floats2half2_rn(v.z, v.w);
        return;
    }
    // prewal: WB[k*32+c] = sum_d W_t[k, head*64+d] * a{l,r}[t][head][d]
    const float *W, *al, *ar; __half* WB; int K, idx;
    if (b < B0 + 16) { W = W0; al = al0; ar = ar0; WB = WB0; K = 128; idx = (b - B0) * 256 + threadIdx.x; }
    else             { W = W1; al = al1; ar = ar1; WB = WB1; K = 256; idx = (b - B0 - 16) * 256 + threadIdx.x; }
    if (idx >= K * 32) return;
    const int k = idx >> 5, c = idx & 31;
    float s = 0.f;
    if (c < 24) {
        const int t = c >> 3, isr = (c >> 2) & 1, hh = c & 3;
        const float* av = (isr ? ar : al) + t * 256 + hh * 64;
        const float* wp = W + ((size_t)t * K + k) * 256 + hh * 64;
        #pragma unroll
        for (int d = 0; d < 64; d += 4) {
            float4 w4 = *reinterpret_cast<const float4*>(wp + d);
            float4 a4 = *reinterpret_cast<const float4*>(av + d);
            s += w4.x * a4.x + w4.y * a4.y + w4.z * a4.z + w4.w * a4.w;
        }
    }
    WB[idx] = __float2half_rn(s);
}

// ---------------- unified projection kernel ---------------------------------
// blockIdx.y in [0,6): HMMA GEMM tile (cp.async double-buffered).
// blockIdx.y == 6:     skinny elr GEMM (elr[N,32] = X @ WB).
#define BM 128
#define BN 128
#define BKH 32
#define APAD 8    // row stride 40 halfs = 80B (odd multiple of 16B -> conflict-free ldsm)
#define BPAD 8    // row stride 136 halfs = 272B (odd)

__global__ __launch_bounds__(256, 2) void hgemm_el(
    const __half* __restrict__ X, const __half* __restrict__ W,
    __half* __restrict__ C, const __half* __restrict__ WB,
    float* __restrict__ elr, int M, int K)
{
    __shared__ __half As[2][BM][BKH + APAD];
    __shared__ __half Bs[2][BKH][BN + BPAD];

    const int tid  = threadIdx.x;
    const int wid  = tid >> 5;
    const int lane = tid & 31;
    const int row0 = blockIdx.x * BM;
    const int ct   = blockIdx.y;

    if (ct == 6) {
        // ---------------- elr path: elr[N,32] = X[N,K] @ WB[K,32] -----------
        __half (*Xs)[BKH + APAD] = reinterpret_cast<__half(*)[BKH + APAD]>(&As[0][0][0]);
        __half (*Ws)[BKH + APAD] = reinterpret_cast<__half(*)[BKH + APAD]>(&Bs[0][0][0]);

        wmma::fragment<wmma::accumulator, 16, 16, 16, float> acc[2];
        wmma::fill_fragment(acc[0], 0.0f);
        wmma::fill_fragment(acc[1], 0.0f);

        const int ar = tid >> 1;
        const int as = (tid & 1) * 16;

        for (int k0 = 0; k0 < K; k0 += 32) {
            uint4 v0 = make_uint4(0u, 0u, 0u, 0u), v1 = v0;
            if (row0 + ar < M) {
                const __half* xp = X + (size_t)(row0 + ar) * K + k0 + as;
                v0 = *reinterpret_cast<const uint4*>(xp);
                v1 = *reinterpret_cast<const uint4*>(xp + 8);
            }
            *reinterpret_cast<uint4*>(&Xs[ar][as])     = v0;
            *reinterpret_cast<uint4*>(&Xs[ar][as + 8]) = v1;
            if (tid < 128) {
                const int r = tid >> 2, cs = (tid & 3) * 8;
                *reinterpret_cast<uint4*>(&Ws[r][cs]) =
                    *reinterpret_cast<const uint4*>(WB + (size_t)(k0 + r) * 32 + cs);
            }
            __syncthreads();

            #pragma unroll
            for (int kk = 0; kk < 32; kk += 16) {
                wmma::fragment<wmma::matrix_a, 16, 16, 16, __half, wmma::row_major> af;
                wmma::fragment<wmma::matrix_b, 16, 16, 16, __half, wmma::row_major> bf0, bf1;
                wmma::load_matrix_sync(af, &Xs[wid * 16][kk], BKH + APAD);
                wmma::load_matrix_sync(bf0, &Ws[kk][0], BKH + APAD);
                wmma::load_matrix_sync(bf1, &Ws[kk][16], BKH + APAD);
                wmma::mma_sync(acc[0], af, bf0, acc[0]);
                wmma::mma_sync(acc[1], af, bf1, acc[1]);
            }
            __syncthreads();
        }

        float* patch = reinterpret_cast<float*>(&As[0][0][0]) + wid * 256;
        const int pr = lane >> 1;
        const int pc = (lane & 1) * 8;
        #pragma unroll
        for (int j = 0; j < 2; j++) {
            wmma::store_matrix_sync(patch, acc[j], 16, wmma::mem_row_major);
            __syncwarp();
            const int grow = row0 + wid * 16 + pr;
            if (grow < M) {
                *reinterpret_cast<float4*>(elr + (size_t)grow * 32 + j * 16 + pc) =
                    *reinterpret_cast<float4*>(&patch[pr * 16 + pc]);
                *reinterpret_cast<float4*>(elr + (size_t)grow * 32 + j * 16 + pc + 4) =
                    *reinterpret_cast<float4*>(&patch[pr * 16 + pc + 4]);
            }
            __syncwarp();
        }
        return;
    }

    // ---------------- main GEMM path: C = X @ W_t, cp.async pipelined -------
    const int t       = ct >> 1;
    const int colbase = (ct & 1) * 128;
    const __half* Wt  = W + (size_t)t * K * 256;

    const int wm = wid >> 1;
    const int wn = wid & 1;

    wmma::fragment<wmma::accumulator, 16, 16, 16, float> acc[2][4];
    #pragma unroll
    for (int i = 0; i < 2; i++)
        #pragma unroll
        for (int j = 0; j < 4; j++) wmma::fill_fragment(acc[i][j], 0.0f);

    const int ar = tid >> 1;
    const int as = (tid & 1) * 16;
    const int br = tid >> 3;
    const int bs = (tid & 7) * 16;

    const bool arow_ok = (row0 + ar < M);
    const int  asz     = arow_ok ? 16 : 0;
    const __half* xrow = X + (size_t)(arow_ok ? row0 + ar : 0) * K + as;
    const __half* wrow = Wt + (size_t)br * 256 + colbase + bs;

    const int NT = K / BKH;

    // stage tile 0
    {
        cp16(smaddr(&As[0][ar][as]),     xrow,     asz);
        cp16(smaddr(&As[0][ar][as + 8]), xrow + 8, asz);
        cp16(smaddr(&Bs[0][br][bs]),     wrow,     16);
        cp16(smaddr(&Bs[0][br][bs + 8]), wrow + 8, 16);
        CPC();
    }

    int buf = 0;
    for (int it = 0; it < NT; it++) {
        if (it + 1 < NT) {
            const int k1 = (it + 1) * BKH;
            cp16(smaddr(&As[buf ^ 1][ar][as]),     xrow + k1,     asz);
            cp16(smaddr(&As[buf ^ 1][ar][as + 8]), xrow + k1 + 8, asz);
            const __half* wp = wrow + (size_t)k1 * 256;
            cp16(smaddr(&Bs[buf ^ 1][br][bs]),     wp,     16);
            cp16(smaddr(&Bs[buf ^ 1][br][bs + 8]), wp + 8, 16);
            CPC();
            CPW(1);
        } else {
            CPW(0);
        }
        __syncthreads();

        #pragma unroll
        for (int kk = 0; kk < BKH; kk += 16) {
            wmma::fragment<wmma::matrix_a, 16, 16, 16, __half, wmma::row_major> af[2];
            wmma::fragment<wmma::matrix_b, 16, 16, 16, __half, wmma::row_major> bf[4];
            #pragma unroll
            for (int i = 0; i < 2; i++)
                wmma::load_matrix_sync(af[i], &As[buf][wm * 32 + i * 16][kk], BKH + APAD);
            #pragma unroll
            for (int j = 0; j < 4; j++)
                wmma::load_matrix_sync(bf[j], &Bs[buf][kk][wn * 64 + j * 16], BN + BPAD);
            #pragma unroll
            for (int i = 0; i < 2; i++)
                #pragma unroll
                for (int j = 0; j < 4; j++)
                    wmma::mma_sync(acc[i][j], af[i], bf[j], acc[i][j]);
        }
        __syncthreads();
        buf ^= 1;
    }

    float* patch = reinterpret_cast<float*>(&As[0][0][0]) + wid * 256;
    const int pr = lane >> 1;
    const int pc = (lane & 1) * 8;

    #pragma unroll
    for (int i = 0; i < 2; i++) {
        #pragma unroll
        for (int j = 0; j < 4; j++) {
            wmma::store_matrix_sync(patch, acc[i][j], 16, wmma::mem_row_major);
            __syncwarp();
            const int grow = row0 + wm * 32 + i * 16 + pr;
            if (grow < M) {
                __half2 hv[4];
                #pragma unroll
                for (int q = 0; q < 4; q++)
                    hv[q] = __floats2half2_rn(patch[pr * 16 + pc + 2 * q],
                                              patch[pr * 16 + pc + 2 * q + 1]);
                *reinterpret_cast<uint4*>(
                    C + (size_t)grow * 768 + ct * 128 + wn * 64 + j * 16 + pc) =
                    *reinterpret_cast<uint4*>(hv);
            }
            __syncwarp();
        }
    }
}

// ---------------- aggregation: 2 nodes/block, warp-autonomous ----------------
__global__ __launch_bounds__(192) void agg_kernel(
    const __half* __restrict__ h, const float* __restrict__ elr,
    const int* __restrict__ src, const float* __restrict__ bias,
    __half* __restrict__ xout, int n)
{
    const int tid   = threadIdx.x;
    const int local = tid / 96;          // node slot within block (0/1)
    const int wt    = (tid % 96) / 32;   // etype
    const int lane  = tid & 31;
    const int i     = blockIdx.x * 2 + local;
    const int E     = n * 16;

    __shared__ int   s_src [2][3][16];
    __shared__ float s_alpha[2][3][4][16];   // [node][t][head][j]
    __shared__ float s_part[2][3][256];

    if (i < n) {
        int s = 0;
        float a[4] = {0.f, 0.f, 0.f, 0.f};
        if (lane < 16) {
            s = src[(size_t)wt * E + i * 16 + lane];
            s_src[local][wt][lane] = s;
            const float4 el4 = *reinterpret_cast<const float4*>(elr + (size_t)s * 32 + wt * 8);
            const float4 er4 = *reinterpret_cast<const float4*>(elr + (size_t)i * 32 + wt * 8 + 4);
            a[0] = el4.x + er4.x;  a[1] = el4.y + er4.y;
            a[2] = el4.z + er4.z;  a[3] = el4.w + er4.w;
            #pragma unroll
            for (int q = 0; q < 4; q++) a[q] = a[q] > 0.f ? a[q] : 0.2f * a[q];
        }
        #pragma unroll
        for (int q = 0; q < 4; q++) {
            float m = a[q];
            #pragma unroll
            for (int o = 1; o < 16; o <<= 1)
                m = fmaxf(m, __shfl_xor_sync(0xffffffffu, m, o, 16));
            float ex = __expf(a[q] - m);
            float sm = ex;
            #pragma unroll
            for (int o = 1; o < 16; o <<= 1)
                sm += __shfl_xor_sync(0xffffffffu, sm, o, 16);
            a[q] = ex / sm;
        }
        if (lane < 16) {
            #pragma unroll
            for (int q = 0; q < 4; q++) s_alpha[local][wt][q][lane] = a[q];
        }
        __syncwarp();

        const float* ap = s_alpha[local][wt][lane >> 3];
        const __half* hb = h + wt * 256 + lane * 8;
        float acc[8] = {0.f, 0.f, 0.f, 0.f, 0.f, 0.f, 0.f, 0.f};
        #pragma unroll
        for (int j = 0; j < 16; j++) {
            const float aw = ap[j];
            uint4 v = *reinterpret_cast<const uint4*>(
                hb + (size_t)s_src[local][wt][j] * 768);
            const __half2* hv = reinterpret_cast<const __half2*>(&v);
            #pragma unroll
            for (int q = 0; q < 4; q++) {
                float2 f = __half22float2(hv[q]);
                acc[2 * q]     += aw * f.x;
                acc[2 * q + 1] += aw * f.y;
            }
        }
        #pragma unroll
        for (int q = 0; q < 8; q++) s_part[local][wt][lane * 8 + q] = acc[q];
    }
    __syncthreads();

    if (tid < 64) {
        const int nl = tid >> 5, oct = tid & 31;
        const int ii = blockIdx.x * 2 + nl;
        if (ii < n) {
            __half2 hv[4];
            #pragma unroll
            for (int q = 0; q < 4; q++) {
                float r[2];
                #pragma unroll
                for (int u = 0; u < 2; u++) {
                    const int c = oct * 8 + 2 * q + u;
                    float sv = s_part[nl][0][c] + s_part[nl][1][c] + s_part[nl][2][c]
                             + bias[c] + bias[256 + c] + bias[512 + c];
                    sv *= (1.0f / 3.0f);
                    r[u] = sv > 0.f ? sv : (__expf(sv) - 1.0f);
                }
                hv[q] = __floats2half2_rn(r[0], r[1]);
            }
            *reinterpret_cast<uint4*>(xout + (size_t)ii * 256 + oct * 8) =
                *reinterpret_cast<uint4*>(hv);
        }
    }
}

// ---------------- layer-2 projection: warp per row, vectorized -------------
__global__ __launch_bounds__(256) void gemm2_kernel(
    const __half* __restrict__ X, const float* __restrict__ W2,
    float* __restrict__ h2, int n)
{
    const int w    = (blockIdx.x * blockDim.x + threadIdx.x) >> 5;
    const int lane = threadIdx.x & 31;
    if (w >= n) return;

    uint4 v = *reinterpret_cast<const uint4*>(X + (size_t)w * 256 + lane * 8);
    const __half2* hv = reinterpret_cast<const __half2*>(&v);

    float s[6] = {0.f, 0.f, 0.f, 0.f, 0.f, 0.f};
    #pragma unroll
    for (int q = 0; q < 4; q++) {
        float2 f = __half22float2(hv[q]);
        const int d = lane * 8 + 2 * q;
        #pragma unroll
        for (int t = 0; t < 3; t++) {
            s[t * 2 + 0] += f.x * W2[t * 512 + d * 2 + 0] + f.y * W2[t * 512 + (d + 1) * 2 + 0];
            s[t * 2 + 1] += f.x * W2[t * 512 + d * 2 + 1] + f.y * W2[t * 512 + (d + 1) * 2 + 1];
        }
    }
    #pragma unroll
    for (int o = 16; o > 0; o >>= 1)
        #pragma unroll
        for (int q = 0; q < 6; q++)
            s[q] += __shfl_xor_sync(0xffffffffu, s[q], o);
    if (lane < 6) h2[(size_t)w * 6 + lane] = s[lane];
}

// ---------------- final: layer-2 attention + outputs ----------------
__global__ __launch_bounds__(128) void final_kernel(
    const float* __restrict__ h2, const float* __restrict__ al2,
    const float* __restrict__ ar2, const float* __restrict__ b2,
    const int* __restrict__ src, float* __restrict__ out,
    int n, int out_size)
{
    const int i = blockIdx.x * blockDim.x + threadIdx.x;
    if (i >= n) return;
    const int E = n * 16;

    float acc0 = 0.f, acc1 = 0.f;
    for (int t = 0; t < 3; t++) {
        const float2 hi = *reinterpret_cast<const float2*>(h2 + (size_t)i * 6 + t * 2);
        const float eri = hi.x * ar2[t * 2 + 0] + hi.y * ar2[t * 2 + 1];
        const float a0 = al2[t * 2 + 0], a1 = al2[t * 2 + 1];

        float e[16], v0[16], v1[16];
        float mx = -1e30f;
        #pragma unroll
        for (int j = 0; j < 16; j++) {
            const int s = src[(size_t)t * E + i * 16 + j];
            const float2 p = *reinterpret_cast<const float2*>(h2 + (size_t)s * 6 + t * 2);
            v0[j] = p.x; v1[j] = p.y;
            float ev = p.x * a0 + p.y * a1 + eri;
            ev = ev > 0.f ? ev : 0.2f * ev;
            e[j] = ev;
            mx = fmaxf(mx, ev);
        }
        float sum = 0.f;
        #pragma unroll
        for (int j = 0; j < 16; j++) { e[j] = __expf(e[j] - mx); sum += e[j]; }
        const float inv = 1.0f / sum;
        float o0 = 0.f, o1 = 0.f;
        #pragma unroll
        for (int j = 0; j < 16; j++) { o0 += e[j] * v0[j]; o1 += e[j] * v1[j]; }
        acc0 += o0 * inv + b2[t * 2 + 0];
        acc1 += o1 * inv + b2[t * 2 + 1];
    }
    out[(size_t)i * 2 + 0] = acc0 * (1.0f / 3.0f);
    out[(size_t)i * 2 + 1] = acc1 * (1.0f / 3.0f);
    if (out_size >= 4 * n) {
        out[(size_t)n * 2 + i * 2 + 0] = 1.0f;
        out[(size_t)n * 2 + i * 2 + 1] = 1.0f;
    }
}

// ---------------- launch ----------------
extern "C" void kernel_launch(void* const* d_in, const int* in_sizes, int n_in,
                              void* d_out, int out_size)
{
    const float* feat = (const float*)d_in[0];
    const float* W0   = (const float*)d_in[1];
    const float* al0  = (const float*)d_in[2];
    const float* ar0  = (const float*)d_in[3];
    const float* b0   = (const float*)d_in[4];
    const float* W1   = (const float*)d_in[5];
    const float* al1  = (const float*)d_in[6];
    const float* ar1  = (const float*)d_in[7];
    const float* b1   = (const float*)d_in[8];
    const float* W2   = (const float*)d_in[9];
    const float* al2  = (const float*)d_in[10];
    const float* ar2  = (const float*)d_in[11];
    const float* b2   = (const float*)d_in[12];
    const int*   src  = (const int*)d_in[13];
    float* out = (float*)d_out;

    const int n = in_sizes[0] / 128;   // 30000

    __half *featH, *w0h, *w1h, *h, *x1h, *x2h, *walh0, *walh1;
    float *elr, *h2;
    cudaGetSymbolAddress((void**)&featH, g_featH);
    cudaGetSymbolAddress((void**)&w0h,   g_w0h);
    cudaGetSymbolAddress((void**)&w1h,   g_w1h);
    cudaGetSymbolAddress((void**)&h,     g_h);
    cudaGetSymbolAddress((void**)&x1h,   g_x1h);
    cudaGetSymbolAddress((void**)&x2h,   g_x2h);
    cudaGetSymbolAddress((void**)&elr,   g_elr);
    cudaGetSymbolAddress((void**)&h2,    g_h2);
    cudaGetSymbolAddress((void**)&walh0, g_walh0);
    cudaGetSymbolAddress((void**)&walh1, g_walh1);

    const dim3 ggrid((n + BM - 1) / BM, 7);   // y=6 is the elr GEMM

    // fused preprocessing: fp16 conversions + composite el/er weights
    const int nf4 = n * 128 / 4;
    const int nw0 = 3 * 128 * 256 / 4;
    const int nw1 = 3 * 256 * 256 / 4;
    const int B0  = (nf4 + nw0 + nw1 + 255) / 256;
    preproc<<<B0 + 48, 256>>>(
        feat, featH, nf4, W0, w0h, nw0, W1, w1h, nw1, B0,
        W0, al0, ar0, walh0, W1, al1, ar1, walh1);

    // layer 0
    hgemm_el<<<ggrid, 256>>>(featH, w0h, h, walh0, elr, n, 128);
    agg_kernel<<<(n + 1) / 2, 192>>>(h, elr, src, b0, x1h, n);

    // layer 1
    hgemm_el<<<ggrid, 256>>>(x1h, w1h, h, walh1, elr, n, 256);
    agg_kernel<<<(n + 1) / 2, 192>>>(h, elr, src, b1, x2h, n);

    // layer 2
    gemm2_kernel<<<(n * 32 + 255) / 256, 256>>>(x2h, W2, h2, n);
    final_kernel<<<(n + 127) / 128, 128>>>(h2, al2, ar2, b2, src, out, n, out_size);
}